// round 15
// baseline (speedup 1.0000x reference)
#include <cuda_runtime.h>
#include <cuda_fp16.h>
#include <cuda_bf16.h>
#include <math.h>

// Problem constants: N=50000, F_IN=F_OUT=128, E=800000
#define FDIM 128
#define NMAX 50000
#define CAP 64          // bucket capacity per row (avg degree 16, P(deg>64)~0)
#define MAX_OVF 65536   // overflow list (effectively never used)

// -------- device scratch (static globals; no runtime alloc) --------
__device__ __align__(16) float g_hi[NMAX * FDIM];            // 25.6 MB support fp32
__device__ __align__(16) __nv_bfloat16 g_sb[NMAX * FDIM];    // 12.8 MB support bf16
__device__ __align__(16) __half g_xh[NMAX * FDIM];           // 12.8 MB fp16 x
__device__ __align__(16) __nv_bfloat16 g_wt[FDIM * FDIM];    // 32 KB bf16(theta*W), [n][k]
__device__ int g_count[NMAX];
__device__ unsigned long long g_bucket[(size_t)NMAX * CAP];
__device__ int g_ovf_count;
__device__ int g_ovf_edges[MAX_OVF];

// ---------------------------------------------------------------------------
// K1: prep — x -> fp16 scratch, zero counters, g_wt = bf16(theta*W^T) [n][k]
// ---------------------------------------------------------------------------
__global__ void prep_kernel(const float* __restrict__ x,
                            const float* __restrict__ W,
                            const float* __restrict__ lam_p,
                            const int* __restrict__ l_p,
                            int n, int nq) {
    int i = blockIdx.x * blockDim.x + threadIdx.x;
    if (i < nq) {                       // nq = n*FDIM/4 float4 chunks
        float4 v = ((const float4*)x)[i];
        __half2 h0 = __floats2half2_rn(v.x, v.y);
        __half2 h1 = __floats2half2_rn(v.z, v.w);
        uint2 o;
        o.x = *(unsigned*)&h0;
        o.y = *(unsigned*)&h1;
        ((uint2*)g_xh)[i] = o;
    }
    if (i < n) g_count[i] = 0;
    if (i == 0) g_ovf_count = 0;
    if (i < FDIM * FDIM) {
        float theta = logf((*lam_p) / (float)(*l_p) + 1.0f);
        int nn = i >> 7;            // output column n
        int k = i & 127;            // input k
        g_wt[nn * FDIM + k] = __float2bfloat16(theta * W[(size_t)k * FDIM + nn]);
    }
}

// ---------------------------------------------------------------------------
// K2: bucket fill. One thread per edge.
// ---------------------------------------------------------------------------
__global__ void fill_buckets_kernel(const int* __restrict__ erow,
                                    const int* __restrict__ ecol,
                                    const float* __restrict__ eval,
                                    int E) {
    int e = blockIdx.x * blockDim.x + threadIdx.x;
    if (e >= E) return;
    int row = erow[e];
    int pos = atomicAdd(&g_count[row], 1);
    if (pos < CAP) {
        unsigned long long packed =
            ((unsigned long long)__float_as_uint(eval[e]) << 32) | (unsigned)ecol[e];
        g_bucket[(size_t)row * CAP + pos] = packed;
    } else {
        int op = atomicAdd(&g_ovf_count, 1);
        if (op < MAX_OVF) g_ovf_edges[op] = e;
    }
}

// ---------------------------------------------------------------------------
// K3: gather SpMM + support, one warp per row, fp16 gathers.
//   S[row] = (1-a)*sum val*x[col] + a*h0[row]  (fp32 accumulate)
// Writes fp32 g_hi (epilogue) and bf16 g_sb (MMA A operand).
// ---------------------------------------------------------------------------
__global__ __launch_bounds__(256)
void gather_support_kernel(const float* __restrict__ x,
                           const float* __restrict__ h0,
                           const float* __restrict__ alpha_p,
                           const int* __restrict__ erow,
                           const int* __restrict__ ecol,
                           const float* __restrict__ eval,
                           int n) {
    int warp = (blockIdx.x * blockDim.x + threadIdx.x) >> 5;
    int lane = threadIdx.x & 31;
    if (warp >= n) return;
    const int row = warp;

    int cnt_raw = g_count[row];
    int cnt = cnt_raw < CAP ? cnt_raw : CAP;

    const unsigned long long* __restrict__ bkt = g_bucket + (size_t)row * CAP;
    const uint2* __restrict__ xh2 = (const uint2*)g_xh;

    float4 acc = make_float4(0.f, 0.f, 0.f, 0.f);
    for (int base = 0; base < cnt; base += 32) {
        int m = cnt - base; if (m > 32) m = 32;
        unsigned long long p = (lane < m) ? bkt[base + lane] : 0ULL;
        #pragma unroll 8
        for (int j = 0; j < m; j++) {
            unsigned long long pj = __shfl_sync(0xffffffffu, p, j);
            int col = (int)(unsigned)pj;
            float v = __uint_as_float((unsigned)(pj >> 32));
            uint2 xv = __ldg(&xh2[(size_t)col * 32 + lane]);
            float2 f0 = __half22float2(*(__half2*)&xv.x);
            float2 f1 = __half22float2(*(__half2*)&xv.y);
            acc.x = fmaf(v, f0.x, acc.x);
            acc.y = fmaf(v, f0.y, acc.y);
            acc.z = fmaf(v, f1.x, acc.z);
            acc.w = fmaf(v, f1.y, acc.w);
        }
    }

    // Overflow fallback (scan; never executes for Poisson(16) degrees)
    if (cnt_raw > CAP) {
        const float4* __restrict__ x4 = (const float4*)x;
        int ovfcnt = g_ovf_count;
        if (ovfcnt > MAX_OVF) ovfcnt = MAX_OVF;
        for (int t = 0; t < ovfcnt; t++) {
            int e = g_ovf_edges[t];
            if (erow[e] == row) {
                float v = eval[e];
                float4 xv = __ldg(&x4[(size_t)ecol[e] * 32 + lane]);
                acc.x = fmaf(v, xv.x, acc.x);
                acc.y = fmaf(v, xv.y, acc.y);
                acc.z = fmaf(v, xv.z, acc.z);
                acc.w = fmaf(v, xv.w, acc.w);
            }
        }
    }

    float a = *alpha_p;
    float oma = 1.0f - a;
    float4 h = __ldg(&((const float4*)h0)[(size_t)row * 32 + lane]);
    float4 s;
    s.x = fmaf(oma, acc.x, a * h.x);
    s.y = fmaf(oma, acc.y, a * h.y);
    s.z = fmaf(oma, acc.z, a * h.z);
    s.w = fmaf(oma, acc.w, a * h.w);
    ((float4*)g_hi)[(size_t)row * 32 + lane] = s;

    __nv_bfloat162 b01 = __floats2bfloat162_rn(s.x, s.y);
    __nv_bfloat162 b23 = __floats2bfloat162_rn(s.z, s.w);
    uint2 ob;
    ob.x = *(unsigned*)&b01;
    ob.y = *(unsigned*)&b23;
    ((uint2*)g_sb)[(size_t)row * 32 + lane] = ob;
}

// ---------------------------------------------------------------------------
// bf16 mma + ldmatrix helpers
// ---------------------------------------------------------------------------
__device__ __forceinline__ void ldsm_x4(unsigned r[4], const void* p) {
    unsigned addr = (unsigned)__cvta_generic_to_shared(p);
    asm volatile("ldmatrix.sync.aligned.m8n8.x4.shared.b16 {%0,%1,%2,%3}, [%4];"
                 : "=r"(r[0]), "=r"(r[1]), "=r"(r[2]), "=r"(r[3]) : "r"(addr));
}

__device__ __forceinline__ void mma_bf16(float c[4], const unsigned a[4],
                                         const unsigned b[2]) {
    asm volatile(
        "mma.sync.aligned.m16n8k16.row.col.f32.bf16.bf16.f32 "
        "{%0,%1,%2,%3}, {%4,%5,%6,%7}, {%8,%9}, {%0,%1,%2,%3};"
        : "+f"(c[0]), "+f"(c[1]), "+f"(c[2]), "+f"(c[3])
        : "r"(a[0]), "r"(a[1]), "r"(a[2]), "r"(a[3]), "r"(b[0]), "r"(b[1]));
}

// ---------------------------------------------------------------------------
// K4: bf16 tensor GEMM + fp32 epilogue.
//   out = Sbf @ (theta*W)bf + (1-theta)*S_fp32 + input
// RB=64 rows/CTA, 256 threads, warps 2(m) x 4(n), warp tile 32x32 via
// m16n8k16 + ldmatrix (all smem access vectorized, conflict-free).
// Whole theta*W (bf16) resident in smem -> ONE __syncthreads total.
// Smem 51KB -> 4 CTAs/SM.
// ---------------------------------------------------------------------------
#define RB 64
#define SB_STRIDE 136   // halves per Ssh row (272B = 68 words, phase conflict-free)
#define WT_STRIDE 136
#define SMEM_BYTES ((RB * SB_STRIDE + FDIM * WT_STRIDE) * 2)

__global__ __launch_bounds__(256, 4)
void gemm_epilogue_kernel(const float* __restrict__ x,
                          const float* __restrict__ lam_p,
                          const int* __restrict__ l_p,
                          float* __restrict__ out,
                          int n) {
    extern __shared__ __nv_bfloat16 smem[];
    __nv_bfloat16* Ssh = smem;                       // RB x SB_STRIDE
    __nv_bfloat16* Wsh = smem + RB * SB_STRIDE;      // FDIM(n) x WT_STRIDE (k)

    const int tid = threadIdx.x;
    const int wid = tid >> 5;
    const int lane = tid & 31;
    const int row0 = blockIdx.x * RB;

    const float theta = logf((*lam_p) / (float)(*l_p) + 1.0f);
    const float omt = 1.0f - theta;

    // ---- Stage S tile (bf16): 64 rows x 128 halves = 1024 uint4, 4/thread ----
    const uint4* __restrict__ sb4 = (const uint4*)g_sb;   // 8 halves per uint4
    #pragma unroll
    for (int i = 0; i < 4; i++) {
        int idx = tid + i * 256;
        int r = idx >> 4;               // 16 uint4 per row
        int q = idx & 15;
        int gr = row0 + r;
        uint4 v = make_uint4(0u, 0u, 0u, 0u);
        if (gr < n) v = sb4[(size_t)gr * 16 + q];
        *(uint4*)(Ssh + r * SB_STRIDE + q * 8) = v;
    }
    // ---- Stage whole theta*W (bf16): 128 rows x 128 halves = 2048 uint4 ----
    const uint4* __restrict__ wt4 = (const uint4*)g_wt;
    #pragma unroll
    for (int i = 0; i < 8; i++) {
        int idx = tid + i * 256;
        int r = idx >> 4;
        int q = idx & 15;
        *(uint4*)(Wsh + r * WT_STRIDE + q * 8) = wt4[(size_t)r * 16 + q];
    }
    __syncthreads();    // the only block sync

    const int g = lane >> 2;       // 0..7
    const int t = lane & 3;        // 0..3
    const int wm = wid & 1;        // 2 warp-rows
    const int wn = wid >> 1;       // 4 warp-cols
    const int m0 = wm * 32;
    const int n0 = wn * 32;

    float c[2][4][4];
    #pragma unroll
    for (int mi = 0; mi < 2; mi++)
        #pragma unroll
        for (int nj = 0; nj < 4; nj++)
            #pragma unroll
            for (int r = 0; r < 4; r++) c[mi][nj][r] = 0.f;

    // ldmatrix lane roles
    const int lr15 = lane & 15;              // row within 16
    const int lc8  = (lane >> 4) << 3;       // +8 col for upper half-warp
    const int br   = (lane & 7) + ((lane & 16) >> 1);  // B: row (lane&7) + 8*(bit4)
    const int bc8  = lane & 8;               // B: +8 col for lanes 8-15/24-31

    #pragma unroll
    for (int ks = 0; ks < 8; ks++) {
        const int kc = ks * 16;

        unsigned a[2][4];
        #pragma unroll
        for (int mi = 0; mi < 2; mi++)
            ldsm_x4(a[mi], Ssh + (m0 + mi * 16 + lr15) * SB_STRIDE + kc + lc8);

        unsigned b[4][2];
        #pragma unroll
        for (int np = 0; np < 2; np++) {
            unsigned r4[4];
            // matrices: rows (n0+np*16 + br), cols kc + bc8
            ldsm_x4(r4, Wsh + (n0 + np * 16 + br) * WT_STRIDE + kc + bc8);
            b[np * 2 + 0][0] = r4[0]; b[np * 2 + 0][1] = r4[1];
            b[np * 2 + 1][0] = r4[2]; b[np * 2 + 1][1] = r4[3];
        }

        #pragma unroll
        for (int mi = 0; mi < 2; mi++)
            #pragma unroll
            for (int nj = 0; nj < 4; nj++)
                mma_bf16(c[mi][nj], a[mi], b[nj]);
    }

    // ---- Epilogue: out = c + (1-theta)*S_fp32 + input ----
    const float2* __restrict__ x2 = (const float2*)x;
    const float2* __restrict__ hi2 = (const float2*)g_hi;
    float2* __restrict__ out2 = (float2*)out;
    #pragma unroll
    for (int mi = 0; mi < 2; mi++) {
        #pragma unroll
        for (int nj = 0; nj < 4; nj++) {
            int cb = n0 + nj * 8 + 2 * t;          // column base (even)
            #pragma unroll
            for (int half = 0; half < 2; half++) { // rows g and g+8
                int lr = m0 + mi * 16 + g + half * 8;
                int gr = row0 + lr;
                if (gr < n) {
                    size_t off = ((size_t)gr * FDIM + cb) >> 1;
                    float2 s = hi2[off];
                    float2 xi = x2[off];
                    float2 o;
                    o.x = c[mi][nj][half * 2 + 0] + omt * s.x + xi.x;
                    o.y = c[mi][nj][half * 2 + 1] + omt * s.y + xi.y;
                    out2[off] = o;
                }
            }
        }
    }
}

// ---------------------------------------------------------------------------
// Launch. Inputs (metadata order):
//  0 input[N,128] f32   1 h0[N,128] f32   2 edge_row[E] i32   3 edge_col[E] i32
//  4 edge_val[E] f32    5 weight[128,128] f32
//  6 lamda f32[1]       7 alpha f32[1]    8 l (int scalar)
// ---------------------------------------------------------------------------
extern "C" void kernel_launch(void* const* d_in, const int* in_sizes, int n_in,
                              void* d_out, int out_size) {
    const float* x     = (const float*)d_in[0];
    const float* h0    = (const float*)d_in[1];
    const int*   erow  = (const int*)d_in[2];
    const int*   ecol  = (const int*)d_in[3];
    const float* eval  = (const float*)d_in[4];
    const float* W     = (const float*)d_in[5];
    const float* lam_p = (const float*)d_in[6];
    const float* alp_p = (const float*)d_in[7];
    const int*   l_p   = (const int*)d_in[8];
    float* out = (float*)d_out;

    int n = in_sizes[0] / FDIM;     // 50000
    int E = in_sizes[2];            // 800000
    int nq = n * FDIM / 4;          // float4 chunks of x

    static int smem_set = 0;
    if (!smem_set) {
        cudaFuncSetAttribute(gemm_epilogue_kernel,
                             cudaFuncAttributeMaxDynamicSharedMemorySize,
                             SMEM_BYTES);
        smem_set = 1;
    }

    prep_kernel<<<(nq + 255) / 256, 256>>>(x, W, lam_p, l_p, n, nq);
    fill_buckets_kernel<<<(E + 255) / 256, 256>>>(erow, ecol, eval, E);
    gather_support_kernel<<<(n + 7) / 8, 256>>>(x, h0, alp_p, erow, ecol, eval, n);
    gemm_epilogue_kernel<<<(n + RB - 1) / RB, 256, SMEM_BYTES>>>(
        x, lam_p, l_p, out, n);
}

// round 16
// speedup vs baseline: 1.0128x; 1.0128x over previous
#include <cuda_runtime.h>
#include <cuda_fp16.h>
#include <cuda_bf16.h>
#include <math.h>

// Problem constants: N=50000, F_IN=F_OUT=128, E=800000
#define FDIM 128
#define NMAX 50000
#define CAP 64          // bucket capacity per row (avg degree 16, P(deg>64)~0)
#define MAX_OVF 65536   // overflow list (effectively never used)

// -------- device scratch (static globals; no runtime alloc) --------
__device__ __align__(16) float g_hi[NMAX * FDIM];            // 25.6 MB support fp32
__device__ __align__(16) __nv_bfloat16 g_sb[NMAX * FDIM];    // 12.8 MB support bf16
__device__ __align__(16) __half g_xh[NMAX * FDIM];           // 12.8 MB fp16 x
__device__ __align__(16) __nv_bfloat16 g_wt[FDIM * FDIM];    // 32 KB bf16(theta*W), [n][k]
__device__ int g_count[NMAX];
__device__ unsigned long long g_bucket[(size_t)NMAX * CAP];
__device__ int g_ovf_count;
__device__ int g_ovf_edges[MAX_OVF];

// ---------------------------------------------------------------------------
// K1: prep — x -> fp16 scratch, zero counters, g_wt = bf16(theta*W^T) [n][k]
// ---------------------------------------------------------------------------
__global__ void prep_kernel(const float* __restrict__ x,
                            const float* __restrict__ W,
                            const float* __restrict__ lam_p,
                            const int* __restrict__ l_p,
                            int n, int nq) {
    int i = blockIdx.x * blockDim.x + threadIdx.x;
    if (i < nq) {                       // nq = n*FDIM/4 float4 chunks
        float4 v = ((const float4*)x)[i];
        __half2 h0 = __floats2half2_rn(v.x, v.y);
        __half2 h1 = __floats2half2_rn(v.z, v.w);
        uint2 o;
        o.x = *(unsigned*)&h0;
        o.y = *(unsigned*)&h1;
        ((uint2*)g_xh)[i] = o;
    }
    if (i < n) g_count[i] = 0;
    if (i == 0) g_ovf_count = 0;
    if (i < FDIM * FDIM) {
        float theta = logf((*lam_p) / (float)(*l_p) + 1.0f);
        int nn = i >> 7;            // output column n
        int k = i & 127;            // input k
        g_wt[nn * FDIM + k] = __float2bfloat16(theta * W[(size_t)k * FDIM + nn]);
    }
}

// ---------------------------------------------------------------------------
// K2: bucket fill. One thread per edge.
// ---------------------------------------------------------------------------
__global__ void fill_buckets_kernel(const int* __restrict__ erow,
                                    const int* __restrict__ ecol,
                                    const float* __restrict__ eval,
                                    int E) {
    int e = blockIdx.x * blockDim.x + threadIdx.x;
    if (e >= E) return;
    int row = erow[e];
    int pos = atomicAdd(&g_count[row], 1);
    if (pos < CAP) {
        unsigned long long packed =
            ((unsigned long long)__float_as_uint(eval[e]) << 32) | (unsigned)ecol[e];
        g_bucket[(size_t)row * CAP + pos] = packed;
    } else {
        int op = atomicAdd(&g_ovf_count, 1);
        if (op < MAX_OVF) g_ovf_edges[op] = e;
    }
}

// ---------------------------------------------------------------------------
// K3: gather SpMM + support, one warp per row, fp16 gathers.
//   S[row] = (1-a)*sum val*x[col] + a*h0[row]  (fp32 accumulate)
// Writes fp32 g_hi (epilogue) and bf16 g_sb (MMA A operand).
// ---------------------------------------------------------------------------
__global__ __launch_bounds__(256)
void gather_support_kernel(const float* __restrict__ x,
                           const float* __restrict__ h0,
                           const float* __restrict__ alpha_p,
                           const int* __restrict__ erow,
                           const int* __restrict__ ecol,
                           const float* __restrict__ eval,
                           int n) {
    int warp = (blockIdx.x * blockDim.x + threadIdx.x) >> 5;
    int lane = threadIdx.x & 31;
    if (warp >= n) return;
    const int row = warp;

    int cnt_raw = g_count[row];
    int cnt = cnt_raw < CAP ? cnt_raw : CAP;

    const unsigned long long* __restrict__ bkt = g_bucket + (size_t)row * CAP;
    const uint2* __restrict__ xh2 = (const uint2*)g_xh;

    float4 acc = make_float4(0.f, 0.f, 0.f, 0.f);
    for (int base = 0; base < cnt; base += 32) {
        int m = cnt - base; if (m > 32) m = 32;
        unsigned long long p = (lane < m) ? bkt[base + lane] : 0ULL;
        #pragma unroll 8
        for (int j = 0; j < m; j++) {
            unsigned long long pj = __shfl_sync(0xffffffffu, p, j);
            int col = (int)(unsigned)pj;
            float v = __uint_as_float((unsigned)(pj >> 32));
            uint2 xv = __ldg(&xh2[(size_t)col * 32 + lane]);
            float2 f0 = __half22float2(*(__half2*)&xv.x);
            float2 f1 = __half22float2(*(__half2*)&xv.y);
            acc.x = fmaf(v, f0.x, acc.x);
            acc.y = fmaf(v, f0.y, acc.y);
            acc.z = fmaf(v, f1.x, acc.z);
            acc.w = fmaf(v, f1.y, acc.w);
        }
    }

    // Overflow fallback (scan; never executes for Poisson(16) degrees)
    if (cnt_raw > CAP) {
        const float4* __restrict__ x4 = (const float4*)x;
        int ovfcnt = g_ovf_count;
        if (ovfcnt > MAX_OVF) ovfcnt = MAX_OVF;
        for (int t = 0; t < ovfcnt; t++) {
            int e = g_ovf_edges[t];
            if (erow[e] == row) {
                float v = eval[e];
                float4 xv = __ldg(&x4[(size_t)ecol[e] * 32 + lane]);
                acc.x = fmaf(v, xv.x, acc.x);
                acc.y = fmaf(v, xv.y, acc.y);
                acc.z = fmaf(v, xv.z, acc.z);
                acc.w = fmaf(v, xv.w, acc.w);
            }
        }
    }

    float a = *alpha_p;
    float oma = 1.0f - a;
    float4 h = __ldg(&((const float4*)h0)[(size_t)row * 32 + lane]);
    float4 s;
    s.x = fmaf(oma, acc.x, a * h.x);
    s.y = fmaf(oma, acc.y, a * h.y);
    s.z = fmaf(oma, acc.z, a * h.z);
    s.w = fmaf(oma, acc.w, a * h.w);
    ((float4*)g_hi)[(size_t)row * 32 + lane] = s;

    __nv_bfloat162 b01 = __floats2bfloat162_rn(s.x, s.y);
    __nv_bfloat162 b23 = __floats2bfloat162_rn(s.z, s.w);
    uint2 ob;
    ob.x = *(unsigned*)&b01;
    ob.y = *(unsigned*)&b23;
    ((uint2*)g_sb)[(size_t)row * 32 + lane] = ob;
}

// ---------------------------------------------------------------------------
// bf16 mma + ldmatrix helpers
// ---------------------------------------------------------------------------
__device__ __forceinline__ void ldsm_x4(unsigned r[4], const void* p) {
    unsigned addr = (unsigned)__cvta_generic_to_shared(p);
    asm volatile("ldmatrix.sync.aligned.m8n8.x4.shared.b16 {%0,%1,%2,%3}, [%4];"
                 : "=r"(r[0]), "=r"(r[1]), "=r"(r[2]), "=r"(r[3]) : "r"(addr));
}

__device__ __forceinline__ void mma_bf16(float c[4], const unsigned a[4],
                                         const unsigned b[2]) {
    asm volatile(
        "mma.sync.aligned.m16n8k16.row.col.f32.bf16.bf16.f32 "
        "{%0,%1,%2,%3}, {%4,%5,%6,%7}, {%8,%9}, {%0,%1,%2,%3};"
        : "+f"(c[0]), "+f"(c[1]), "+f"(c[2]), "+f"(c[3])
        : "r"(a[0]), "r"(a[1]), "r"(a[2]), "r"(a[3]), "r"(b[0]), "r"(b[1]));
}

// ---------------------------------------------------------------------------
// K4: bf16 tensor GEMM + fp32 epilogue.
//   out = Sbf @ (theta*W)bf + (1-theta)*S_fp32 + input
// RB=64 rows/CTA, 256 threads, warps 2(m) x 4(n), warp tile 32x32 via
// m16n8k16 + ldmatrix (all smem access vectorized, conflict-free).
// Whole theta*W (bf16) resident in smem -> ONE __syncthreads total.
// Smem 51KB -> 4 CTAs/SM.
// ---------------------------------------------------------------------------
#define RB 64
#define SB_STRIDE 136   // halves per Ssh row (272B = 68 words, phase conflict-free)
#define WT_STRIDE 136
#define SMEM_BYTES ((RB * SB_STRIDE + FDIM * WT_STRIDE) * 2)

__global__ __launch_bounds__(256, 4)
void gemm_epilogue_kernel(const float* __restrict__ x,
                          const float* __restrict__ lam_p,
                          const int* __restrict__ l_p,
                          float* __restrict__ out,
                          int n) {
    extern __shared__ __nv_bfloat16 smem[];
    __nv_bfloat16* Ssh = smem;                       // RB x SB_STRIDE
    __nv_bfloat16* Wsh = smem + RB * SB_STRIDE;      // FDIM(n) x WT_STRIDE (k)

    const int tid = threadIdx.x;
    const int wid = tid >> 5;
    const int lane = tid & 31;
    const int row0 = blockIdx.x * RB;

    const float theta = logf((*lam_p) / (float)(*l_p) + 1.0f);
    const float omt = 1.0f - theta;

    // ---- Stage S tile (bf16): 64 rows x 128 halves = 1024 uint4, 4/thread ----
    const uint4* __restrict__ sb4 = (const uint4*)g_sb;   // 8 halves per uint4
    #pragma unroll
    for (int i = 0; i < 4; i++) {
        int idx = tid + i * 256;
        int r = idx >> 4;               // 16 uint4 per row
        int q = idx & 15;
        int gr = row0 + r;
        uint4 v = make_uint4(0u, 0u, 0u, 0u);
        if (gr < n) v = sb4[(size_t)gr * 16 + q];
        *(uint4*)(Ssh + r * SB_STRIDE + q * 8) = v;
    }
    // ---- Stage whole theta*W (bf16): 128 rows x 128 halves = 2048 uint4 ----
    const uint4* __restrict__ wt4 = (const uint4*)g_wt;
    #pragma unroll
    for (int i = 0; i < 8; i++) {
        int idx = tid + i * 256;
        int r = idx >> 4;
        int q = idx & 15;
        *(uint4*)(Wsh + r * WT_STRIDE + q * 8) = wt4[(size_t)r * 16 + q];
    }
    __syncthreads();    // the only block sync

    const int g = lane >> 2;       // 0..7
    const int t = lane & 3;        // 0..3
    const int wm = wid & 1;        // 2 warp-rows
    const int wn = wid >> 1;       // 4 warp-cols
    const int m0 = wm * 32;
    const int n0 = wn * 32;

    float c[2][4][4];
    #pragma unroll
    for (int mi = 0; mi < 2; mi++)
        #pragma unroll
        for (int nj = 0; nj < 4; nj++)
            #pragma unroll
            for (int r = 0; r < 4; r++) c[mi][nj][r] = 0.f;

    // ldmatrix lane roles
    const int lr15 = lane & 15;              // row within 16
    const int lc8  = (lane >> 4) << 3;       // +8 col for upper half-warp
    const int br   = (lane & 7) + ((lane & 16) >> 1);  // B: row (lane&7) + 8*(bit4)
    const int bc8  = lane & 8;               // B: +8 col for lanes 8-15/24-31

    #pragma unroll
    for (int ks = 0; ks < 8; ks++) {
        const int kc = ks * 16;

        unsigned a[2][4];
        #pragma unroll
        for (int mi = 0; mi < 2; mi++)
            ldsm_x4(a[mi], Ssh + (m0 + mi * 16 + lr15) * SB_STRIDE + kc + lc8);

        unsigned b[4][2];
        #pragma unroll
        for (int np = 0; np < 2; np++) {
            unsigned r4[4];
            // matrices: rows (n0+np*16 + br), cols kc + bc8
            ldsm_x4(r4, Wsh + (n0 + np * 16 + br) * WT_STRIDE + kc + bc8);
            b[np * 2 + 0][0] = r4[0]; b[np * 2 + 0][1] = r4[1];
            b[np * 2 + 1][0] = r4[2]; b[np * 2 + 1][1] = r4[3];
        }

        #pragma unroll
        for (int mi = 0; mi < 2; mi++)
            #pragma unroll
            for (int nj = 0; nj < 4; nj++)
                mma_bf16(c[mi][nj], a[mi], b[nj]);
    }

    // ---- Epilogue: out = c + (1-theta)*S_fp32 + input ----
    const float2* __restrict__ x2 = (const float2*)x;
    const float2* __restrict__ hi2 = (const float2*)g_hi;
    float2* __restrict__ out2 = (float2*)out;
    #pragma unroll
    for (int mi = 0; mi < 2; mi++) {
        #pragma unroll
        for (int nj = 0; nj < 4; nj++) {
            int cb = n0 + nj * 8 + 2 * t;          // column base (even)
            #pragma unroll
            for (int half = 0; half < 2; half++) { // rows g and g+8
                int lr = m0 + mi * 16 + g + half * 8;
                int gr = row0 + lr;
                if (gr < n) {
                    size_t off = ((size_t)gr * FDIM + cb) >> 1;
                    float2 s = hi2[off];
                    float2 xi = x2[off];
                    float2 o;
                    o.x = c[mi][nj][half * 2 + 0] + omt * s.x + xi.x;
                    o.y = c[mi][nj][half * 2 + 1] + omt * s.y + xi.y;
                    out2[off] = o;
                }
            }
        }
    }
}

// ---------------------------------------------------------------------------
// Launch. Inputs (metadata order):
//  0 input[N,128] f32   1 h0[N,128] f32   2 edge_row[E] i32   3 edge_col[E] i32
//  4 edge_val[E] f32    5 weight[128,128] f32
//  6 lamda f32[1]       7 alpha f32[1]    8 l (int scalar)
// ---------------------------------------------------------------------------
extern "C" void kernel_launch(void* const* d_in, const int* in_sizes, int n_in,
                              void* d_out, int out_size) {
    const float* x     = (const float*)d_in[0];
    const float* h0    = (const float*)d_in[1];
    const int*   erow  = (const int*)d_in[2];
    const int*   ecol  = (const int*)d_in[3];
    const float* eval  = (const float*)d_in[4];
    const float* W     = (const float*)d_in[5];
    const float* lam_p = (const float*)d_in[6];
    const float* alp_p = (const float*)d_in[7];
    const int*   l_p   = (const int*)d_in[8];
    float* out = (float*)d_out;

    int n = in_sizes[0] / FDIM;     // 50000
    int E = in_sizes[2];            // 800000
    int nq = n * FDIM / 4;          // float4 chunks of x

    static int smem_set = 0;
    if (!smem_set) {
        cudaFuncSetAttribute(gemm_epilogue_kernel,
                             cudaFuncAttributeMaxDynamicSharedMemorySize,
                             SMEM_BYTES);
        smem_set = 1;
    }

    prep_kernel<<<(nq + 255) / 256, 256>>>(x, W, lam_p, l_p, n, nq);
    fill_buckets_kernel<<<(E + 255) / 256, 256>>>(erow, ecol, eval, E);
    gather_support_kernel<<<(n + 7) / 8, 256>>>(x, h0, alp_p, erow, ecol, eval, n);
    gemm_epilogue_kernel<<<(n + RB - 1) / RB, 256, SMEM_BYTES>>>(
        x, lam_p, l_p, out, n);
}

// round 17
// speedup vs baseline: 1.1087x; 1.0947x over previous
#include <cuda_runtime.h>
#include <cuda_fp16.h>
#include <cuda_bf16.h>
#include <math.h>

// Problem constants: N=50000, F_IN=F_OUT=128, E=800000
#define FDIM 128
#define NMAX 50000
#define CAP 64          // bucket capacity per row (avg degree 16, P(deg>64)~0)
#define MAX_OVF 65536   // overflow list (effectively never used)

// -------- device scratch (static globals; no runtime alloc) --------
__device__ __align__(16) float g_hi[NMAX * FDIM];            // 25.6 MB support fp32
__device__ __align__(16) __half g_xh[NMAX * FDIM];           // 12.8 MB fp16 x
__device__ __align__(16) __nv_bfloat16 g_wt[FDIM * FDIM];    // 32 KB bf16(theta*W), [n][k]
__device__ int g_count[NMAX];
__device__ unsigned long long g_bucket[(size_t)NMAX * CAP];
__device__ int g_ovf_count;
__device__ int g_ovf_edges[MAX_OVF];

// ---------------------------------------------------------------------------
// K1: prep — x -> fp16 scratch, zero counters, g_wt = bf16(theta*W^T) [n][k]
// ---------------------------------------------------------------------------
__global__ void prep_kernel(const float* __restrict__ x,
                            const float* __restrict__ W,
                            const float* __restrict__ lam_p,
                            const int* __restrict__ l_p,
                            int n, int nq) {
    int i = blockIdx.x * blockDim.x + threadIdx.x;
    if (i < nq) {                       // nq = n*FDIM/4 float4 chunks
        float4 v = ((const float4*)x)[i];
        __half2 h0 = __floats2half2_rn(v.x, v.y);
        __half2 h1 = __floats2half2_rn(v.z, v.w);
        uint2 o;
        o.x = *(unsigned*)&h0;
        o.y = *(unsigned*)&h1;
        ((uint2*)g_xh)[i] = o;
    }
    if (i < n) g_count[i] = 0;
    if (i == 0) g_ovf_count = 0;
    if (i < FDIM * FDIM) {
        float theta = logf((*lam_p) / (float)(*l_p) + 1.0f);
        int nn = i >> 7;            // output column n
        int k = i & 127;            // input k
        g_wt[nn * FDIM + k] = __float2bfloat16(theta * W[(size_t)k * FDIM + nn]);
    }
}

// ---------------------------------------------------------------------------
// K2: bucket fill. One thread per edge.
// ---------------------------------------------------------------------------
__global__ void fill_buckets_kernel(const int* __restrict__ erow,
                                    const int* __restrict__ ecol,
                                    const float* __restrict__ eval,
                                    int E) {
    int e = blockIdx.x * blockDim.x + threadIdx.x;
    if (e >= E) return;
    int row = erow[e];
    int pos = atomicAdd(&g_count[row], 1);
    if (pos < CAP) {
        unsigned long long packed =
            ((unsigned long long)__float_as_uint(eval[e]) << 32) | (unsigned)ecol[e];
        g_bucket[(size_t)row * CAP + pos] = packed;
    } else {
        int op = atomicAdd(&g_ovf_count, 1);
        if (op < MAX_OVF) g_ovf_edges[op] = e;
    }
}

// ---------------------------------------------------------------------------
// K3: gather SpMM + support. TWO rows per warp: each half-warp owns one row,
// lanes load uint4 (8 fp16) of x[col]. Doubles per-warp MLP vs one-row/warp.
//   g_hi[row] = (1-a)*sum val*x[col] + a*h0[row]   (fp32 accumulate)
// ---------------------------------------------------------------------------
__global__ __launch_bounds__(256)
void gather_support_kernel(const float* __restrict__ x,
                           const float* __restrict__ h0,
                           const float* __restrict__ alpha_p,
                           const int* __restrict__ erow,
                           const int* __restrict__ ecol,
                           const float* __restrict__ eval,
                           int n) {
    int gw = (blockIdx.x * blockDim.x + threadIdx.x) >> 5;   // warp id
    int lane = threadIdx.x & 31;
    int h = lane >> 4;            // half-warp id (0/1)
    int sl = lane & 15;           // sub-lane within half
    int row = gw * 2 + h;
    if (row >= n) return;         // whole half-warp exits together

    const unsigned hmask = 0xFFFFu << (h * 16);

    int cnt_raw = g_count[row];
    int cnt = cnt_raw < CAP ? cnt_raw : CAP;

    const unsigned long long* __restrict__ bkt = g_bucket + (size_t)row * CAP;
    const uint4* __restrict__ xh4 = (const uint4*)g_xh;      // 16 uint4 per row

    float acc[8];
    #pragma unroll
    for (int i = 0; i < 8; i++) acc[i] = 0.f;

    for (int base = 0; base < cnt; base += 16) {
        int m = cnt - base; if (m > 16) m = 16;
        unsigned long long p = (sl < m) ? bkt[base + sl] : 0ULL;
        #pragma unroll 4
        for (int j = 0; j < m; j++) {
            unsigned long long pj = __shfl_sync(hmask, p, h * 16 + j);
            int col = (int)(unsigned)pj;
            float v = __uint_as_float((unsigned)(pj >> 32));
            uint4 xv = __ldg(&xh4[(size_t)col * 16 + sl]);
            float2 f0 = __half22float2(*(__half2*)&xv.x);
            float2 f1 = __half22float2(*(__half2*)&xv.y);
            float2 f2 = __half22float2(*(__half2*)&xv.z);
            float2 f3 = __half22float2(*(__half2*)&xv.w);
            acc[0] = fmaf(v, f0.x, acc[0]);
            acc[1] = fmaf(v, f0.y, acc[1]);
            acc[2] = fmaf(v, f1.x, acc[2]);
            acc[3] = fmaf(v, f1.y, acc[3]);
            acc[4] = fmaf(v, f2.x, acc[4]);
            acc[5] = fmaf(v, f2.y, acc[5]);
            acc[6] = fmaf(v, f3.x, acc[6]);
            acc[7] = fmaf(v, f3.y, acc[7]);
        }
    }

    // Overflow fallback (scan; never executes for Poisson(16) degrees)
    if (cnt_raw > CAP) {
        const float4* __restrict__ x4 = (const float4*)x;
        int ovfcnt = g_ovf_count;
        if (ovfcnt > MAX_OVF) ovfcnt = MAX_OVF;
        for (int t = 0; t < ovfcnt; t++) {
            int e = g_ovf_edges[t];
            if (erow[e] == row) {
                float v = eval[e];
                float4 xa = __ldg(&x4[(size_t)ecol[e] * 32 + sl * 2]);
                float4 xb = __ldg(&x4[(size_t)ecol[e] * 32 + sl * 2 + 1]);
                acc[0] = fmaf(v, xa.x, acc[0]);
                acc[1] = fmaf(v, xa.y, acc[1]);
                acc[2] = fmaf(v, xa.z, acc[2]);
                acc[3] = fmaf(v, xa.w, acc[3]);
                acc[4] = fmaf(v, xb.x, acc[4]);
                acc[5] = fmaf(v, xb.y, acc[5]);
                acc[6] = fmaf(v, xb.z, acc[6]);
                acc[7] = fmaf(v, xb.w, acc[7]);
            }
        }
    }

    float a = *alpha_p;
    float oma = 1.0f - a;
    const float4* __restrict__ h04 = (const float4*)h0;
    float4 ha = __ldg(&h04[(size_t)row * 32 + sl * 2]);
    float4 hb = __ldg(&h04[(size_t)row * 32 + sl * 2 + 1]);
    float4 s0, s1;
    s0.x = fmaf(oma, acc[0], a * ha.x);
    s0.y = fmaf(oma, acc[1], a * ha.y);
    s0.z = fmaf(oma, acc[2], a * ha.z);
    s0.w = fmaf(oma, acc[3], a * ha.w);
    s1.x = fmaf(oma, acc[4], a * hb.x);
    s1.y = fmaf(oma, acc[5], a * hb.y);
    s1.z = fmaf(oma, acc[6], a * hb.z);
    s1.w = fmaf(oma, acc[7], a * hb.w);
    ((float4*)g_hi)[(size_t)row * 32 + sl * 2] = s0;
    ((float4*)g_hi)[(size_t)row * 32 + sl * 2 + 1] = s1;
}

// ---------------------------------------------------------------------------
// bf16 mma + ldmatrix helpers
// ---------------------------------------------------------------------------
__device__ __forceinline__ void ldsm_x4(unsigned r[4], const void* p) {
    unsigned addr = (unsigned)__cvta_generic_to_shared(p);
    asm volatile("ldmatrix.sync.aligned.m8n8.x4.shared.b16 {%0,%1,%2,%3}, [%4];"
                 : "=r"(r[0]), "=r"(r[1]), "=r"(r[2]), "=r"(r[3]) : "r"(addr));
}

__device__ __forceinline__ void mma_bf16(float c[4], const unsigned a[4],
                                         const unsigned b[2]) {
    asm volatile(
        "mma.sync.aligned.m16n8k16.row.col.f32.bf16.bf16.f32 "
        "{%0,%1,%2,%3}, {%4,%5,%6,%7}, {%8,%9}, {%0,%1,%2,%3};"
        : "+f"(c[0]), "+f"(c[1]), "+f"(c[2]), "+f"(c[3])
        : "r"(a[0]), "r"(a[1]), "r"(a[2]), "r"(a[3]), "r"(b[0]), "r"(b[1]));
}

// ---------------------------------------------------------------------------
// K4: PERSISTENT bf16 tensor GEMM + fp32 epilogue.
//   out = Sbf @ (theta*W)bf + (1-theta)*S_fp32 + input
// Grid = exactly one wave (4 CTAs/SM). Each CTA stages whole theta*W once,
// then loops over 64-row tiles: stage S (fp32 g_hi -> bf16 smem), mma via
// ldmatrix, fp32 epilogue from L2-hot g_hi. Smem 51KB.
// ---------------------------------------------------------------------------
#define RB 64
#define SB_STRIDE 136
#define WT_STRIDE 136
#define SMEM_BYTES ((RB * SB_STRIDE + FDIM * WT_STRIDE) * 2)

__global__ __launch_bounds__(256, 4)
void gemm_epilogue_kernel(const float* __restrict__ x,
                          const float* __restrict__ lam_p,
                          const int* __restrict__ l_p,
                          float* __restrict__ out,
                          int n) {
    extern __shared__ __nv_bfloat16 smem[];
    __nv_bfloat16* Ssh = smem;                       // RB x SB_STRIDE
    __nv_bfloat16* Wsh = smem + RB * SB_STRIDE;      // FDIM(n) x WT_STRIDE (k)

    const int tid = threadIdx.x;
    const int wid = tid >> 5;
    const int lane = tid & 31;

    const float theta = logf((*lam_p) / (float)(*l_p) + 1.0f);
    const float omt = 1.0f - theta;

    // ---- Stage whole theta*W once: 128 rows x 128 halves = 2048 uint4 ----
    const uint4* __restrict__ wt4 = (const uint4*)g_wt;
    #pragma unroll
    for (int i = 0; i < 8; i++) {
        int idx = tid + i * 256;
        int r = idx >> 4;
        int q = idx & 15;
        *(uint4*)(Wsh + r * WT_STRIDE + q * 8) = wt4[(size_t)r * 16 + q];
    }

    const int g = lane >> 2;       // 0..7
    const int t = lane & 3;        // 0..3
    const int wm = wid & 1;        // 2 warp-rows
    const int wn = wid >> 1;       // 4 warp-cols
    const int m0 = wm * 32;
    const int n0 = wn * 32;

    // ldmatrix lane roles
    const int lr15 = lane & 15;
    const int lc8  = (lane >> 4) << 3;
    const int br   = (lane & 7) + ((lane & 16) >> 1);
    const int bc8  = lane & 8;

    const float4* __restrict__ hi4 = (const float4*)g_hi;
    const float2* __restrict__ x2 = (const float2*)x;
    const float2* __restrict__ hi2 = (const float2*)g_hi;
    float2* __restrict__ out2 = (float2*)out;

    const int ntiles = (n + RB - 1) / RB;
    for (int tile = blockIdx.x; tile < ntiles; tile += gridDim.x) {
        const int row0 = tile * RB;

        __syncthreads();   // previous tile's mma readers done with Ssh

        // ---- Stage S tile: fp32 g_hi -> bf16 Ssh. 2048 float4, 8/thread ----
        #pragma unroll
        for (int i = 0; i < 8; i++) {
            int idx = tid + i * 256;
            int r = idx >> 5;               // 32 float4 per row
            int c4 = idx & 31;
            int gr = row0 + r;
            float4 v = make_float4(0.f, 0.f, 0.f, 0.f);
            if (gr < n) v = hi4[(size_t)gr * 32 + c4];
            __nv_bfloat162 b01 = __floats2bfloat162_rn(v.x, v.y);
            __nv_bfloat162 b23 = __floats2bfloat162_rn(v.z, v.w);
            uint2 ob;
            ob.x = *(unsigned*)&b01;
            ob.y = *(unsigned*)&b23;
            *(uint2*)(Ssh + r * SB_STRIDE + c4 * 4) = ob;
        }
        __syncthreads();

        float c[2][4][4];
        #pragma unroll
        for (int mi = 0; mi < 2; mi++)
            #pragma unroll
            for (int nj = 0; nj < 4; nj++)
                #pragma unroll
                for (int r = 0; r < 4; r++) c[mi][nj][r] = 0.f;

        #pragma unroll
        for (int ks = 0; ks < 8; ks++) {
            const int kc = ks * 16;

            unsigned a[2][4];
            #pragma unroll
            for (int mi = 0; mi < 2; mi++)
                ldsm_x4(a[mi], Ssh + (m0 + mi * 16 + lr15) * SB_STRIDE + kc + lc8);

            unsigned b[4][2];
            #pragma unroll
            for (int np = 0; np < 2; np++) {
                unsigned r4[4];
                ldsm_x4(r4, Wsh + (n0 + np * 16 + br) * WT_STRIDE + kc + bc8);
                b[np * 2 + 0][0] = r4[0]; b[np * 2 + 0][1] = r4[1];
                b[np * 2 + 1][0] = r4[2]; b[np * 2 + 1][1] = r4[3];
            }

            #pragma unroll
            for (int mi = 0; mi < 2; mi++)
                #pragma unroll
                for (int nj = 0; nj < 4; nj++)
                    mma_bf16(c[mi][nj], a[mi], b[nj]);
        }

        // ---- Epilogue: out = c + (1-theta)*S_fp32 + input ----
        #pragma unroll
        for (int mi = 0; mi < 2; mi++) {
            #pragma unroll
            for (int nj = 0; nj < 4; nj++) {
                int cb = n0 + nj * 8 + 2 * t;          // column base (even)
                #pragma unroll
                for (int half = 0; half < 2; half++) { // rows g and g+8
                    int lr = m0 + mi * 16 + g + half * 8;
                    int gr = row0 + lr;
                    if (gr < n) {
                        size_t off = ((size_t)gr * FDIM + cb) >> 1;
                        float2 s = hi2[off];
                        float2 xi = x2[off];
                        float2 o;
                        o.x = c[mi][nj][half * 2 + 0] + omt * s.x + xi.x;
                        o.y = c[mi][nj][half * 2 + 1] + omt * s.y + xi.y;
                        out2[off] = o;
                    }
                }
            }
        }
    }
}

// ---------------------------------------------------------------------------
// Launch. Inputs (metadata order):
//  0 input[N,128] f32   1 h0[N,128] f32   2 edge_row[E] i32   3 edge_col[E] i32
//  4 edge_val[E] f32    5 weight[128,128] f32
//  6 lamda f32[1]       7 alpha f32[1]    8 l (int scalar)
// ---------------------------------------------------------------------------
extern "C" void kernel_launch(void* const* d_in, const int* in_sizes, int n_in,
                              void* d_out, int out_size) {
    const float* x     = (const float*)d_in[0];
    const float* h0    = (const float*)d_in[1];
    const int*   erow  = (const int*)d_in[2];
    const int*   ecol  = (const int*)d_in[3];
    const float* eval  = (const float*)d_in[4];
    const float* W     = (const float*)d_in[5];
    const float* lam_p = (const float*)d_in[6];
    const float* alp_p = (const float*)d_in[7];
    const int*   l_p   = (const int*)d_in[8];
    float* out = (float*)d_out;

    int n = in_sizes[0] / FDIM;     // 50000
    int E = in_sizes[2];            // 800000
    int nq = n * FDIM / 4;          // float4 chunks of x

    static int smem_set = 0;
    if (!smem_set) {
        cudaFuncSetAttribute(gemm_epilogue_kernel,
                             cudaFuncAttributeMaxDynamicSharedMemorySize,
                             SMEM_BYTES);
        smem_set = 1;
    }

    prep_kernel<<<(nq + 255) / 256, 256>>>(x, W, lam_p, l_p, n, nq);
    fill_buckets_kernel<<<(E + 255) / 256, 256>>>(erow, ecol, eval, E);
    // 2 rows per warp -> ceil(n/2) warps
    int gwarps = (n + 1) / 2;
    gather_support_kernel<<<(gwarps * 32 + 255) / 256, 256>>>(
        x, h0, alp_p, erow, ecol, eval, n);
    // persistent grid: one full wave at 4 CTAs/SM on 148 SMs
    gemm_epilogue_kernel<<<592, 256, SMEM_BYTES>>>(x, lam_p, l_p, out, n);
}